// round 2
// baseline (speedup 1.0000x reference)
#include <cuda_runtime.h>
#include <cstdint>

// Focal CTC loss — register-resident alpha recursion.
//   grid = B (64 CTAs), 256 threads: warps 0-6 hold the 201 extended states in
//   registers (1 state/thread), neighbor exchange via shfl_up; only the 2
//   warp-boundary values per warp go through shared memory, guarded by a
//   narrow bar.sync(1,224). Warp 7 runs a barrier-free exp-sum loop.
//   Emissions + exp-sum operands are LDG-prefetched 8 steps ahead into
//   registers (no smem ring, no cp.async). 3-way LSE in log2 domain with the
//   max term folded to ex2(0)=1 (3 MUFU/state). Final scalar factorizes:
//   mean(outer(w, loss)) = mean(loss)*mean(w); reduced by the last CTA.

#define CFIX  256
#define NEG2  (-1e30f)
#define LOG2E 1.4426950408889634f
#define LN2   0.6931471805599453f
#define PF    8

__device__ float g_loss[1024];
__device__ float g_wsum[1024];
__device__ unsigned int g_ctr = 0;

__device__ __forceinline__ float ex2f(float x){ float y; asm("ex2.approx.ftz.f32 %0,%1;":"=f"(y):"f"(x)); return y; }
__device__ __forceinline__ float lg2f(float x){ float y; asm("lg2.approx.ftz.f32 %0,%1;":"=f"(y):"f"(x)); return y; }

__global__ __launch_bounds__(256, 1)
void focal_ctc_kernel(const float* __restrict__ lp,      // (T,B,C)
                      const int*   __restrict__ targets, // (B*L)
                      const int*   __restrict__ in_len,  // (B)
                      const int*   __restrict__ tg_len,  // (B)
                      float*       __restrict__ out,
                      int T, int B, int L)
{
    __shared__ float bnd[2][8][2];   // per-warp boundary states (lanes 30,31), double buffered
    __shared__ float sums[CFIX];     // per-channel sum_t exp(lp)
    __shared__ float lastv[2];       // alpha at t=len-1 for states 2*tl, 2*tl-1
    __shared__ float redw[8];

    const int b = blockIdx.x, tid = threadIdx.x;
    const int w = tid >> 5, lane = tid & 31;
    const int S = 2 * L + 1;
    const int len = in_len[b], tl = tg_len[b];
    const size_t tstr = (size_t)B * CFIX;
    const float* base = lp + (size_t)b * CFIX;

    const bool recw = (w < 7);           // warps 0-6 carry states
    const int  s = tid;                  // state id
    int extS = 0; bool allow2 = false;
    const bool isState = recw && (s < S);
    if (isState) {
        if (s & 1) extS = targets[b * L + (s >> 1)];
        if (s >= 2 && extS != 0) {
            int ep = ((s - 2) & 1) ? targets[b * L + ((s - 2) >> 1)] : 0;
            allow2 = (extS != ep);
        }
    }

    const float* ptid = base + tid;      // this thread's exp-sum channel
    const float* pext = base + extS;     // this state's emission channel

    // ---- t = 0 ----
    float sExp = ex2f(ptid[0] * LOG2E);
    float cur  = NEG2;

    if (recw) {
        float e0 = pext[0];
        cur = (isState && s < 2) ? e0 * LOG2E : NEG2;
        if (lane >= 30) bnd[0][w][lane & 1] = cur;
        if (len == 1) {
            if (s == 2 * tl)     lastv[0] = cur;
            if (s == 2 * tl - 1) lastv[1] = cur;
        }

        // register prefetch pipeline, PF steps ahead
        float eP[PF], rP[PF];
        #pragma unroll
        for (int j = 0; j < PF; j++) {
            size_t tt = 1 + j; if (tt > (size_t)(T - 1)) tt = T - 1;
            eP[j] = pext[tt * tstr];
            rP[j] = ptid[tt * tstr];
        }

        int t = 1;
        for (; t + PF <= T; t += PF) {
            #pragma unroll
            for (int j = 0; j < PF; j++) {
                const int tc = t + j;
                float a1 = __shfl_up_sync(0xFFFFFFFFu, cur, 1);
                float a2 = __shfl_up_sync(0xFFFFFFFFu, cur, 2);
                asm volatile("bar.sync 1, 224;" ::: "memory");
                const int par = (tc - 1) & 1;
                if (lane < 2) {
                    if (w == 0) { a2 = NEG2; if (lane == 0) a1 = NEG2; }
                    else {
                        float hb = bnd[par][w - 1][1];
                        if (lane == 0) { a1 = hb; a2 = bnd[par][w - 1][0]; }
                        else            a2 = hb;
                    }
                }
                if (!allow2) a2 = NEG2;
                float e = eP[j], rr = rP[j];
                { // prefetch t+PF
                    size_t tn = (size_t)tc + PF; if (tn > (size_t)(T - 1)) tn = T - 1;
                    eP[j] = pext[tn * tstr]; rP[j] = ptid[tn * tstr];
                }
                sExp += ex2f(rr * LOG2E);
                // 3-way LSE, max term folded to 1
                float hi = fmaxf(cur, a1), lo = fminf(cur, a1);
                float m  = fmaxf(hi, a2), o1 = fminf(hi, a2);
                float ss = 1.0f + ex2f(o1 - m) + ex2f(lo - m);
                float nv = fmaf(e, LOG2E, m + lg2f(ss));
                if (!isState) nv = NEG2;
                cur = nv;
                if (lane >= 30) bnd[tc & 1][w][lane & 1] = nv;
                if (tc == len - 1) {
                    if (s == 2 * tl)     lastv[0] = nv;
                    if (s == 2 * tl - 1) lastv[1] = nv;
                }
            }
        }
        // tail (< PF steps), compile-time register indices
        #pragma unroll
        for (int j = 0; j < PF; j++) {
            const int tc = t + j;
            if (tc < T) {
                float a1 = __shfl_up_sync(0xFFFFFFFFu, cur, 1);
                float a2 = __shfl_up_sync(0xFFFFFFFFu, cur, 2);
                asm volatile("bar.sync 1, 224;" ::: "memory");
                const int par = (tc - 1) & 1;
                if (lane < 2) {
                    if (w == 0) { a2 = NEG2; if (lane == 0) a1 = NEG2; }
                    else {
                        float hb = bnd[par][w - 1][1];
                        if (lane == 0) { a1 = hb; a2 = bnd[par][w - 1][0]; }
                        else            a2 = hb;
                    }
                }
                if (!allow2) a2 = NEG2;
                float e = eP[j], rr = rP[j];
                sExp += ex2f(rr * LOG2E);
                float hi = fmaxf(cur, a1), lo = fminf(cur, a1);
                float m  = fmaxf(hi, a2), o1 = fminf(hi, a2);
                float ss = 1.0f + ex2f(o1 - m) + ex2f(lo - m);
                float nv = fmaf(e, LOG2E, m + lg2f(ss));
                if (!isState) nv = NEG2;
                cur = nv;
                if (lane >= 30) bnd[tc & 1][w][lane & 1] = nv;
                if (tc == len - 1) {
                    if (s == 2 * tl)     lastv[0] = nv;
                    if (s == 2 * tl - 1) lastv[1] = nv;
                }
            }
        }
    } else {
        // warp 7: barrier-free exp-sum for channels 224..255
        float rP[PF];
        #pragma unroll
        for (int j = 0; j < PF; j++) {
            size_t tt = 1 + j; if (tt > (size_t)(T - 1)) tt = T - 1;
            rP[j] = ptid[tt * tstr];
        }
        int t = 1;
        for (; t + PF <= T; t += PF) {
            #pragma unroll
            for (int j = 0; j < PF; j++) {
                float rr = rP[j];
                size_t tn = (size_t)(t + j) + PF; if (tn > (size_t)(T - 1)) tn = T - 1;
                rP[j] = ptid[tn * tstr];
                sExp += ex2f(rr * LOG2E);
            }
        }
        #pragma unroll
        for (int j = 0; j < PF; j++) if (t + j < T) sExp += ex2f(rP[j] * LOG2E);
    }

    // ---- epilogue: focal weights + per-sample loss ----
    sums[tid] = sExp;
    __syncthreads();

    float wgt = 0.0f;
    if (tid < L) {
        int   c  = targets[b * L + tid];
        float p  = sums[c] * (1.0f / (float)T);
        float om = 1.0f - p;
        wgt = om * om;                      // GAMMA = 2
    }
    #pragma unroll
    for (int o = 16; o; o >>= 1) wgt += __shfl_down_sync(0xFFFFFFFFu, wgt, o);
    if (lane == 0) redw[w] = wgt;
    __syncthreads();

    if (tid == 0) {
        float ws = 0.0f;
        #pragma unroll
        for (int i = 0; i < 8; i++) ws += redw[i];
        float la = lastv[0], lb = lastv[1];
        float m  = fmaxf(la, lb);
        float ll = (m + lg2f(ex2f(la - m) + ex2f(lb - m))) * LN2;
        float loss = (ll > -5e29f) ? -ll : 0.0f;   // zero_infinity
        g_loss[b] = loss;
        g_wsum[b] = ws;
        __threadfence();
        unsigned v = atomicAdd(&g_ctr, 1u);
        if (v == (unsigned)(B - 1)) {              // last CTA finalizes
            g_ctr = 0;                             // reset for next graph replay
            __threadfence();
            float ls = 0.0f, wt = 0.0f;
            for (int i = 0; i < B; i++) {
                ls += __ldcg(&g_loss[i]);
                wt += __ldcg(&g_wsum[i]);
            }
            out[0] = (ls / (float)B) * (wt / ((float)B * (float)L));
        }
    }
}

extern "C" void kernel_launch(void* const* d_in, const int* in_sizes, int n_in,
                              void* d_out, int out_size)
{
    const float* lp      = (const float*)d_in[0];
    const int*   targets = (const int*)d_in[1];
    const int*   in_len  = (const int*)d_in[2];
    const int*   tg_len  = (const int*)d_in[3];

    int B = in_sizes[2];                 // 64
    int L = in_sizes[1] / B;             // 100
    int T = in_sizes[0] / (B * CFIX);    // 1000

    focal_ctc_kernel<<<B, 256>>>(lp, targets, in_len, tg_len, (float*)d_out, T, B, L);
}

// round 3
// speedup vs baseline: 2.4954x; 2.4954x over previous
#include <cuda_runtime.h>
#include <cstdint>

// Focal CTC loss — warp-specialized scan + parallel focal-weight reduction.
// grid = 2B: CTAs [0,B) run the alpha recursion (warps 0-6 compute 201 states
// in smem double buffer, warp 7 owns the cp.async row ring: issue/commit/wait).
// CTAs [B,2B) compute sum_t exp(log_probs[t,b,c]) coalesced and the focal
// weight sum per sample. Final scalar = mean(loss)*mean(w) (outer-product mean
// factorizes); last-arriving CTA combines via atomic counter.

#define CFIX  256
#define DEPTH 8
#define NEG2  (-1e30f)
#define LOG2E 1.4426950408889634f
#define LN2   0.6931471805599453f

__device__ float g_loss[1024];
__device__ float g_wsum[1024];
__device__ unsigned int g_ctr = 0;

__device__ __forceinline__ float ex2f(float x){ float y; asm("ex2.approx.ftz.f32 %0,%1;":"=f"(y):"f"(x)); return y; }
__device__ __forceinline__ float lg2f(float x){ float y; asm("lg2.approx.ftz.f32 %0,%1;":"=f"(y):"f"(x)); return y; }

__device__ __forceinline__ void finalize(float* out, int B, int L, int nCTA)
{
    __threadfence();
    unsigned v = atomicAdd(&g_ctr, 1u);
    if (v == (unsigned)(nCTA - 1)) {
        g_ctr = 0;                       // reset for next graph replay
        __threadfence();
        float ls = 0.0f, ws = 0.0f;
        for (int i = 0; i < B; i++) {
            ls += __ldcg(&g_loss[i]);
            ws += __ldcg(&g_wsum[i]);
        }
        out[0] = (ls / (float)B) * (ws / ((float)B * (float)L));
    }
}

__global__ __launch_bounds__(256, 1)
void focal_ctc_kernel(const float* __restrict__ lp,      // (T,B,C)
                      const int*   __restrict__ targets, // (B*L)
                      const int*   __restrict__ in_len,  // (B)
                      const int*   __restrict__ tg_len,  // (B)
                      float*       __restrict__ out,
                      int T, int B, int L)
{
    __shared__ float ring[DEPTH][CFIX];  // log_probs row ring (8 KB)
    __shared__ float abuf[2][264];       // alpha double buffer, 2-pad front
    __shared__ float sums[CFIX];         // reduce-CTA: per-channel exp sums
    __shared__ float lastv[2];
    __shared__ float redw[8];

    const int tid = threadIdx.x, w = tid >> 5, lane = tid & 31;
    const int bid = blockIdx.x;
    const size_t tstr = (size_t)B * CFIX;

    // ================= reduce CTAs: focal weights =================
    if (bid >= B) {
        const int b = bid - B;
        const float* p = lp + (size_t)b * CFIX + tid;
        float acc = 0.0f;
        int t = 0;
        for (; t + 8 <= T; t += 8) {
            float v[8];
            #pragma unroll
            for (int j = 0; j < 8; j++) v[j] = __ldcg(p + (size_t)(t + j) * tstr);
            #pragma unroll
            for (int j = 0; j < 8; j++) acc += ex2f(v[j] * LOG2E);
        }
        for (; t < T; t++) acc += ex2f(__ldcg(p + (size_t)t * tstr) * LOG2E);
        sums[tid] = acc;
        __syncthreads();
        float wgt = 0.0f;
        if (tid < L) {
            int   c  = targets[b * L + tid];
            float pr = sums[c] * (1.0f / (float)T);
            float om = 1.0f - pr;
            wgt = om * om;                       // GAMMA = 2
        }
        #pragma unroll
        for (int o = 16; o; o >>= 1) wgt += __shfl_down_sync(0xFFFFFFFFu, wgt, o);
        if (lane == 0) redw[w] = wgt;
        __syncthreads();
        if (tid == 0) {
            float ws = 0.0f;
            #pragma unroll
            for (int i = 0; i < 8; i++) ws += redw[i];
            g_wsum[b] = ws;
            finalize(out, B, L, 2 * B);
        }
        return;
    }

    // ================= recursion CTAs =================
    const int b   = bid;
    const int S   = 2 * L + 1;
    const int len = in_len[b], tl = tg_len[b];
    const bool w7 = (w == 7);

    const bool isState = (tid < S);
    int extS = 0; bool allow2 = false;
    if (isState) {
        if (tid & 1) extS = targets[b * L + (tid >> 1)];
        if (tid >= 2 && extS != 0) {
            int ep = ((tid - 2) & 1) ? targets[b * L + ((tid - 2) >> 1)] : 0;
            allow2 = (extS != ep);
        }
    }
    if (tid < 2) { abuf[0][tid] = NEG2; abuf[1][tid] = NEG2; }

    const float* rowb = lp + (size_t)b * CFIX;

    // warp 7 prologue: rows 0..DEPTH-2 in flight
    if (w7) {
        #pragma unroll
        for (int r = 0; r < DEPTH - 1; r++) {
            if (r < T) {
                const float* s0 = rowb + (size_t)r * tstr + lane * 4;
                uint32_t d0 = (uint32_t)__cvta_generic_to_shared(&ring[r][lane * 4]);
                asm volatile("cp.async.ca.shared.global [%0], [%1], 16;" :: "r"(d0), "l"(s0) : "memory");
                asm volatile("cp.async.ca.shared.global [%0], [%1], 16;" :: "r"(d0 + 512), "l"(s0 + 128) : "memory");
            }
            asm volatile("cp.async.commit_group;" ::: "memory");
        }
        asm volatile("cp.async.wait_group %0;" :: "n"(DEPTH - 2) : "memory");
    }
    __syncthreads();                                    // row 0 visible

    // t = 0
    float e0  = ring[0][extS];
    float cur = (isState && tid < 2) ? e0 * LOG2E : NEG2;
    abuf[0][2 + tid] = cur;
    if (len == 1) {
        if (tid == 2 * tl)     lastv[0] = cur;
        if (tid == 2 * tl - 1) lastv[1] = cur;
    }

    for (int t = 1; t < T; t++) {
        __syncthreads();    // abuf(t-1) + ring row t visible; row t-2 reads done
        if (w7) {
            // issue row t+DEPTH-2 into its slot (previously row t-2: safe)
            const int r = t + DEPTH - 2;
            if (r < T) {
                const float* s0 = rowb + (size_t)r * tstr + lane * 4;
                uint32_t d0 = (uint32_t)__cvta_generic_to_shared(&ring[r & (DEPTH - 1)][lane * 4]);
                asm volatile("cp.async.ca.shared.global [%0], [%1], 16;" :: "r"(d0), "l"(s0) : "memory");
                asm volatile("cp.async.ca.shared.global [%0], [%1], 16;" :: "r"(d0 + 512), "l"(s0 + 128) : "memory");
            }
            asm volatile("cp.async.commit_group;" ::: "memory");
            asm volatile("cp.async.wait_group %0;" :: "n"(DEPTH - 2) : "memory");
        } else {
            const float* pr = abuf[(t - 1) & 1];
            float e  = ring[t & (DEPTH - 1)][extS];
            float a1 = pr[1 + tid];
            float a2 = allow2 ? pr[tid] : NEG2;
            float hi = fmaxf(cur, a1), lo = fminf(cur, a1);
            float m  = fmaxf(hi, a2),  o1 = fminf(hi, a2);
            float ss = 1.0f + ex2f(o1 - m) + ex2f(lo - m);
            float nv = fmaf(e, LOG2E, m + lg2f(ss));
            nv = isState ? nv : NEG2;
            abuf[t & 1][2 + tid] = nv;
            cur = nv;
            if (t == len - 1) {
                if (tid == 2 * tl)     lastv[0] = nv;
                if (tid == 2 * tl - 1) lastv[1] = nv;
            }
        }
    }
    __syncthreads();

    if (tid == 0) {
        float la = lastv[0], lb = lastv[1];
        float m  = fmaxf(la, lb);
        float ll = (m + lg2f(ex2f(la - m) + ex2f(lb - m))) * LN2;
        g_loss[b] = (ll > -5e29f) ? -ll : 0.0f;   // zero_infinity
        finalize(out, B, L, 2 * B);
    }
}

extern "C" void kernel_launch(void* const* d_in, const int* in_sizes, int n_in,
                              void* d_out, int out_size)
{
    const float* lp      = (const float*)d_in[0];
    const int*   targets = (const int*)d_in[1];
    const int*   in_len  = (const int*)d_in[2];
    const int*   tg_len  = (const int*)d_in[3];

    int B = in_sizes[2];                 // 64
    int L = in_sizes[1] / B;             // 100
    int T = in_sizes[0] / (B * CFIX);    // 1000

    focal_ctc_kernel<<<2 * B, 256>>>(lp, targets, in_len, tg_len, (float*)d_out, T, B, L);
}